// round 3
// baseline (speedup 1.0000x reference)
#include <cuda_runtime.h>
#include <math.h>

#define N_NODES 50000
#define N_EDGES 800000
#define ND 128
#define ED 64
#define HID 320
#define PCOLS 512

typedef unsigned long long u64;

// Scratch (device globals: allocation-guard safe)
__device__ float g_P[(size_t)N_NODES * PCOLS];   // node projections [N, 512]
__device__ float g_Wn[128 * 512];                // packed node weights  [k][j]
__device__ float g_We2[64 * 256];                // packed edge weights  [k][j] (j<128 val, j>=128 mul)

// ---- packed f32x2 helpers (sm_103a dual-issue fp32) -----------------------
__device__ __forceinline__ u64 fma2(u64 a, u64 b, u64 c) {
    u64 d;
    asm("fma.rn.f32x2 %0, %1, %2, %3;" : "=l"(d) : "l"(a), "l"(b), "l"(c));
    return d;
}
__device__ __forceinline__ u64 add2(u64 a, u64 b) {
    u64 d;
    asm("add.rn.f32x2 %0, %1, %2;" : "=l"(d) : "l"(a), "l"(b));
    return d;
}
__device__ __forceinline__ u64 pack2(float lo, float hi) {
    u64 d;
    asm("mov.b64 %0, {%1, %2};" : "=l"(d) : "f"(lo), "f"(hi));
    return d;
}
__device__ __forceinline__ void unpack2(u64 v, float& lo, float& hi) {
    asm("mov.b64 {%0, %1}, %2;" : "=f"(lo), "=f"(hi) : "l"(v));
}

// ---------------------------------------------------------------------------
// Pack weights: Wn[k][j] and We2[k][j] from W_val/W_mul (each [128][320]).
// c = [x_s(0:128), x_r(128:256), ef(256:320)]
// ---------------------------------------------------------------------------
__global__ void pack_weights_kernel(const float* __restrict__ Wv,
                                    const float* __restrict__ Wm) {
    int i = blockIdx.x * blockDim.x + threadIdx.x;
    if (i < 128 * 512) {
        int k = i >> 9, j = i & 511;
        float v;
        if (j < 128)      v = Wv[j * HID + k];               // Ws_val
        else if (j < 256) v = Wv[(j - 128) * HID + 128 + k]; // Wr_val
        else if (j < 384) v = Wm[(j - 256) * HID + k];       // Ws_mul
        else              v = Wm[(j - 384) * HID + 128 + k]; // Wr_mul
        g_Wn[i] = v;
    }
    if (i < 64 * 256) {
        int k = i >> 8, j = i & 255;
        g_We2[i] = (j < 128) ? Wv[j * HID + 256 + k]
                             : Wm[(j - 128) * HID + 256 + k];
    }
}

__global__ void zero_out_kernel(float4* __restrict__ out, int n4) {
    int i = blockIdx.x * blockDim.x + threadIdx.x;
    if (i < n4) out[i] = make_float4(0.f, 0.f, 0.f, 0.f);
}

// ---------------------------------------------------------------------------
// Node GEMM: P[50000,512] = X[50000,128] @ Wn[128,512]   (FFMA2 inner loop)
// 128x128 block tile, 8x8 per-thread micro-tile, BK=16.
// As2 holds duplicated {v,v} pairs so the broadcast operand loads as LDS.64.
// ---------------------------------------------------------------------------
__global__ __launch_bounds__(256) void node_gemm_kernel(const float* __restrict__ X) {
    __shared__ float2 As2[16][132];   // [k][m] duplicated, padded
    __shared__ float  Bs[16][128];    // [k][n]
    int m0 = blockIdx.x * 128;
    int n0 = blockIdx.y * 128;
    int tid = threadIdx.x;
    int tm = tid >> 4;   // 0..15
    int tn = tid & 15;   // 0..15

    u64 acc[8][4];
    #pragma unroll
    for (int i = 0; i < 8; i++)
        #pragma unroll
        for (int j = 0; j < 4; j++) acc[i][j] = 0ull;

    for (int k0 = 0; k0 < 128; k0 += 16) {
        #pragma unroll
        for (int i = 0; i < 8; i++) {
            int lin = tid + i * 256;
            int k = lin & 15, m = lin >> 4;
            int gm = m0 + m;
            float v = (gm < N_NODES) ? X[(size_t)gm * ND + k0 + k] : 0.f;
            As2[k][m] = make_float2(v, v);
        }
        #pragma unroll
        for (int i = 0; i < 8; i++) {
            int lin = tid + i * 256;
            int n = lin & 127, k = lin >> 7;
            Bs[k][n] = g_Wn[(k0 + k) * 512 + n0 + n];
        }
        __syncthreads();
        #pragma unroll
        for (int k = 0; k < 16; k++) {
            u64 a2[8];
            #pragma unroll
            for (int i = 0; i < 8; i++)
                a2[i] = *(const u64*)&As2[k][tm * 8 + i];
            ulonglong2 b0 = *(const ulonglong2*)&Bs[k][tn * 8];
            ulonglong2 b1 = *(const ulonglong2*)&Bs[k][tn * 8 + 4];
            #pragma unroll
            for (int i = 0; i < 8; i++) {
                acc[i][0] = fma2(a2[i], b0.x, acc[i][0]);
                acc[i][1] = fma2(a2[i], b0.y, acc[i][1]);
                acc[i][2] = fma2(a2[i], b1.x, acc[i][2]);
                acc[i][3] = fma2(a2[i], b1.y, acc[i][3]);
            }
        }
        __syncthreads();
    }

    #pragma unroll
    for (int i = 0; i < 8; i++) {
        int gm = m0 + tm * 8 + i;
        if (gm < N_NODES) {
            *(ulonglong2*)&g_P[(size_t)gm * 512 + n0 + tn * 8] =
                make_ulonglong2(acc[i][0], acc[i][1]);
            *(ulonglong2*)&g_P[(size_t)gm * 512 + n0 + tn * 8 + 4] =
                make_ulonglong2(acc[i][2], acc[i][3]);
        }
    }
}

// ---------------------------------------------------------------------------
// Fused edge kernel (persistent): per 64-edge tile,
//   Q = ef_tile[64,64] @ We2[64,256]  (FFMA2 register fragments)
//   logits = Q + gathered P terms + bias;  msg = softplus(v)*sigmoid(m)
//   atomicAdd into out[receiver].
// Thread (eg = tid/32, dg = tid%32) owns edges eg*8..+7, dims dg*4..+3
// (val AND mul). Warp covers all 128 dims -> gathers + atomics coalesced.
// efT2 stores duplicated {v,v} pairs -> broadcast operand is one LDS.64.
// ---------------------------------------------------------------------------
#define TE 64
#define EDGE_SMEM (64 * 256 * 4 + 64 * 64 * 8 + 64 * 2 * 4)

__global__ __launch_bounds__(256, 2) void edge_kernel(
    const float* __restrict__ ef, const int* __restrict__ ei,
    const float* __restrict__ b_val, const float* __restrict__ b_mul,
    float* __restrict__ out)
{
    extern __shared__ float sh[];
    float*  W_sh = sh;                       // [64][256]
    float2* efT2 = (float2*)(sh + 64 * 256); // [64][64] duplicated pairs
    int*    s_sh = (int*)(efT2 + 64 * 64);   // [64]
    int*    r_sh = s_sh + 64;                // [64]

    int tid = threadIdx.x;
    int eg = tid >> 5;        // 0..7  (edge group)
    int dg = tid & 31;        // 0..31 (dim group)
    int d0 = dg * 4;

    // Load edge weights once per block
    for (int i = tid; i < 64 * 256; i += 256) W_sh[i] = g_We2[i];

    const float4 bv4 = *(const float4*)&b_val[d0];
    const float4 bm4 = *(const float4*)&b_mul[d0];
    const u64 bv01 = pack2(bv4.x, bv4.y), bv23 = pack2(bv4.z, bv4.w);
    const u64 bm01 = pack2(bm4.x, bm4.y), bm23 = pack2(bm4.z, bm4.w);

    __syncthreads();

    const int ntiles = N_EDGES / TE;   // 12500
    for (int tile = blockIdx.x; tile < ntiles; tile += gridDim.x) {
        int e0 = tile * TE;

        if (tid < 64) {
            s_sh[tid] = ei[e0 + tid];
            r_sh[tid] = ei[N_EDGES + e0 + tid];
        }
        for (int i = tid; i < 64 * 64; i += 256) {
            int e = i >> 6, k = i & 63;
            float v = ef[(size_t)(e0 + e) * ED + k];
            efT2[k * 64 + e] = make_float2(v, v);
        }
        __syncthreads();

        u64 accv[8][2], accm[8][2];
        #pragma unroll
        for (int i = 0; i < 8; i++) {
            accv[i][0] = accv[i][1] = 0ull;
            accm[i][0] = accm[i][1] = 0ull;
        }

        const float2* efb = efT2 + eg * 8;
        #pragma unroll 4
        for (int k = 0; k < 64; k++) {
            u64 a2[8];
            #pragma unroll
            for (int i = 0; i < 8; i++)
                a2[i] = *(const u64*)&efb[k * 64 + i];
            ulonglong2 bl = *(const ulonglong2*)&W_sh[k * 256 + d0];        // val dims
            ulonglong2 bh = *(const ulonglong2*)&W_sh[k * 256 + 128 + d0];  // mul dims
            #pragma unroll
            for (int i = 0; i < 8; i++) {
                accv[i][0] = fma2(a2[i], bl.x, accv[i][0]);
                accv[i][1] = fma2(a2[i], bl.y, accv[i][1]);
                accm[i][0] = fma2(a2[i], bh.x, accm[i][0]);
                accm[i][1] = fma2(a2[i], bh.y, accm[i][1]);
            }
        }

        // Epilogue: gather P (packed adds), activations, scatter
        #pragma unroll
        for (int i = 0; i < 8; i++) {
            int el = eg * 8 + i;
            int s = s_sh[el];
            int r = r_sh[el];
            ulonglong2 psv = *(const ulonglong2*)&g_P[(size_t)s * 512 + d0];
            ulonglong2 prv = *(const ulonglong2*)&g_P[(size_t)r * 512 + 128 + d0];
            ulonglong2 psm = *(const ulonglong2*)&g_P[(size_t)s * 512 + 256 + d0];
            ulonglong2 prm = *(const ulonglong2*)&g_P[(size_t)r * 512 + 384 + d0];

            u64 v01 = add2(add2(accv[i][0], bv01), add2(psv.x, prv.x));
            u64 v23 = add2(add2(accv[i][1], bv23), add2(psv.y, prv.y));
            u64 m01 = add2(add2(accm[i][0], bm01), add2(psm.x, prm.x));
            u64 m23 = add2(add2(accm[i][1], bm23), add2(psm.y, prm.y));

            float v0, v1, v2, v3, m0_, m1_, m2_, m3_;
            unpack2(v01, v0, v1); unpack2(v23, v2, v3);
            unpack2(m01, m0_, m1_); unpack2(m23, m2_, m3_);

            // softplus(v) * sigmoid(m), fast-math MUFU path
            float g0, g1, g2, g3;
            {
                float t0 = __expf(-fabsf(v0)), t1 = __expf(-fabsf(v1));
                float t2 = __expf(-fabsf(v2)), t3 = __expf(-fabsf(v3));
                float sp0 = fmaxf(v0, 0.f) + __logf(1.f + t0);
                float sp1 = fmaxf(v1, 0.f) + __logf(1.f + t1);
                float sp2 = fmaxf(v2, 0.f) + __logf(1.f + t2);
                float sp3 = fmaxf(v3, 0.f) + __logf(1.f + t3);
                float sg0 = __fdividef(1.f, 1.f + __expf(-m0_));
                float sg1 = __fdividef(1.f, 1.f + __expf(-m1_));
                float sg2 = __fdividef(1.f, 1.f + __expf(-m2_));
                float sg3 = __fdividef(1.f, 1.f + __expf(-m3_));
                g0 = sp0 * sg0; g1 = sp1 * sg1; g2 = sp2 * sg2; g3 = sp3 * sg3;
            }

            float* op = out + (size_t)r * ND + d0;
            atomicAdd(op + 0, g0);
            atomicAdd(op + 1, g1);
            atomicAdd(op + 2, g2);
            atomicAdd(op + 3, g3);
        }
        __syncthreads();   // protect efT2 / idx before next tile's loads
    }
}

// ---------------------------------------------------------------------------
extern "C" void kernel_launch(void* const* d_in, const int* in_sizes, int n_in,
                              void* d_out, int out_size) {
    const float* x  = (const float*)d_in[0];
    const int*   ei = (const int*)  d_in[1];
    const float* ef = (const float*)d_in[2];
    const float* Wv = (const float*)d_in[3];
    const float* bv = (const float*)d_in[4];
    const float* Wm = (const float*)d_in[5];
    const float* bm = (const float*)d_in[6];
    float* out = (float*)d_out;

    cudaFuncSetAttribute(edge_kernel,
                         cudaFuncAttributeMaxDynamicSharedMemorySize, EDGE_SMEM);

    pack_weights_kernel<<<(128 * 512 + 255) / 256, 256>>>(Wv, Wm);

    int n4 = N_NODES * ND / 4;
    zero_out_kernel<<<(n4 + 255) / 256, 256>>>((float4*)out, n4);

    node_gemm_kernel<<<dim3((N_NODES + 127) / 128, 4), 256>>>(x);

    edge_kernel<<<296, 256, EDGE_SMEM>>>(ef, ei, bv, bm, out);
}

// round 5
// speedup vs baseline: 1.6074x; 1.6074x over previous
#include <cuda_runtime.h>
#include <cuda_bf16.h>
#include <stdint.h>

#define N_NODES 50000
#define N_EDGES 800000
#define ND 128
#define ED 64
#define HID 320

typedef uint32_t u32;

// ---------------- device globals (allocation-guard safe) -------------------
__device__ float g_P[(size_t)N_NODES * 512];     // node projections [N,512] fp32
__device__ __nv_bfloat16 g_WnH[512 * 128];       // node weights hi  [j][k]
__device__ __nv_bfloat16 g_WnL[512 * 128];       // node weights lo
__device__ __nv_bfloat16 g_WeH[256 * 64];        // edge weights hi  [j][k]
__device__ __nv_bfloat16 g_WeL[256 * 64];        // edge weights lo

// ---------------- helpers ----------------------------------------------------
__device__ __forceinline__ u32 smem_u32(const void* p) {
    u32 a;
    asm("{ .reg .u64 t; cvta.to.shared.u64 t, %1; cvt.u32.u64 %0, t; }" : "=r"(a) : "l"(p));
    return a;
}
__device__ __forceinline__ void ldsm4(u32 addr, u32& r0, u32& r1, u32& r2, u32& r3) {
    asm volatile("ldmatrix.sync.aligned.m8n8.x4.shared.b16 {%0,%1,%2,%3}, [%4];"
                 : "=r"(r0), "=r"(r1), "=r"(r2), "=r"(r3) : "r"(addr));
}
__device__ __forceinline__ void ldsm2(u32 addr, u32& r0, u32& r1) {
    asm volatile("ldmatrix.sync.aligned.m8n8.x2.shared.b16 {%0,%1}, [%2];"
                 : "=r"(r0), "=r"(r1) : "r"(addr));
}
__device__ __forceinline__ void mma16816(float* d, u32 a0, u32 a1, u32 a2, u32 a3,
                                         u32 b0, u32 b1) {
    asm volatile(
        "mma.sync.aligned.m16n8k16.row.col.f32.bf16.bf16.f32 "
        "{%0,%1,%2,%3}, {%4,%5,%6,%7}, {%8,%9}, {%0,%1,%2,%3};"
        : "+f"(d[0]), "+f"(d[1]), "+f"(d[2]), "+f"(d[3])
        : "r"(a0), "r"(a1), "r"(a2), "r"(a3), "r"(b0), "r"(b1));
}
__device__ __forceinline__ void red4(float* p, float a, float b, float c, float d) {
    asm volatile("red.global.add.v4.f32 [%0], {%1,%2,%3,%4};"
                 :: "l"(p), "f"(a), "f"(b), "f"(c), "f"(d) : "memory");
}
__device__ __forceinline__ void split_bf16(float v, __nv_bfloat16& h, __nv_bfloat16& l) {
    h = __float2bfloat16_rn(v);
    l = __float2bfloat16_rn(v - __bfloat162float(h));
}
__device__ __forceinline__ float softplus_f(float x) {
    return fmaxf(x, 0.f) + __logf(1.f + __expf(-fabsf(x)));
}
__device__ __forceinline__ float sigmoid_f(float x) {
    return __fdividef(1.f, 1.f + __expf(-x));
}

// ---------------------------------------------------------------------------
// pack: bf16 hi/lo weights with column permutation
// Wn[j][k]: j<128 Ws_val, <256 Wr_val, <384 Ws_mul, <512 Wr_mul (k = node dim)
// We[j][k]: j<128 edge part of W_val, else W_mul (k = edge dim)
// ---------------------------------------------------------------------------
__global__ void pack_weights_kernel(const float* __restrict__ Wv,
                                    const float* __restrict__ Wm) {
    int i = blockIdx.x * blockDim.x + threadIdx.x;
    if (i < 512 * 128) {
        int j = i >> 7, k = i & 127;
        float v;
        if (j < 128)      v = Wv[j * HID + k];
        else if (j < 256) v = Wv[(j - 128) * HID + 128 + k];
        else if (j < 384) v = Wm[(j - 256) * HID + k];
        else              v = Wm[(j - 384) * HID + 128 + k];
        __nv_bfloat16 h, l; split_bf16(v, h, l);
        g_WnH[i] = h; g_WnL[i] = l;
    }
    if (i < 256 * 64) {
        int j = i >> 6, k = i & 63;
        float v = (j < 128) ? Wv[j * HID + 256 + k] : Wm[(j - 128) * HID + 256 + k];
        __nv_bfloat16 h, l; split_bf16(v, h, l);
        g_WeH[i] = h; g_WeL[i] = l;
    }
}

__global__ void zero_out_kernel(float4* __restrict__ out, int n4) {
    int i = blockIdx.x * blockDim.x + threadIdx.x;
    if (i < n4) out[i] = make_float4(0.f, 0.f, 0.f, 0.f);
}

// ---------------------------------------------------------------------------
// Node GEMM (HMMA bf16x3): P[m, n0:n0+256] = X[50000,128] @ Wn^T
// 512 thr = 16 warps; tile 128 nodes x 256 j; warp = 16n x 128j (egrp x jgrp).
// ---------------------------------------------------------------------------
#define NSTR 136                     // padded bf16 row stride (128 + 8)
#define N_BH 0
#define N_BL 69632
#define N_AH 139264
#define N_AL 174080
#define NODE_SMEM 208896

__global__ __launch_bounds__(512, 1) void node_gemm_kernel(const float* __restrict__ X) {
    extern __shared__ char smem[];
    u32 sb = smem_u32(smem);
    int tid = threadIdx.x, wid = tid >> 5, lane = tid & 31;
    int n0 = blockIdx.y * 256;

    // fill B (Wn half [256][128]) hi/lo, padded rows
    {
        int j = tid >> 1, k0 = (tid & 1) * 64;
        #pragma unroll
        for (int c = 0; c < 64; c += 2) {
            __nv_bfloat162 h2, l2;
            h2.x = g_WnH[(n0 + j) * 128 + k0 + c];
            h2.y = g_WnH[(n0 + j) * 128 + k0 + c + 1];
            l2.x = g_WnL[(n0 + j) * 128 + k0 + c];
            l2.y = g_WnL[(n0 + j) * 128 + k0 + c + 1];
            *(__nv_bfloat162*)(smem + N_BH + (j * NSTR + k0 + c) * 2) = h2;
            *(__nv_bfloat162*)(smem + N_BL + (j * NSTR + k0 + c) * 2) = l2;
        }
    }

    int egrp = wid >> 1, jgrp = wid & 1;
    u32 aH = sb + N_AH + ((egrp * 16 + (lane & 15)) * NSTR + (lane >> 4) * 8) * 2;
    u32 aL = sb + N_AL + ((egrp * 16 + (lane & 15)) * NSTR + (lane >> 4) * 8) * 2;
    u32 bH = sb + N_BH + ((jgrp * 128 + (lane & 7)) * NSTR + (lane & 8)) * 2;
    u32 bL = sb + N_BL + ((jgrp * 128 + (lane & 7)) * NSTR + (lane & 8)) * 2;

    const int ntiles = (N_NODES + 127) / 128;   // 391
    for (int t = blockIdx.x; t < ntiles; t += gridDim.x) {
        int m0 = t * 128;
        // fill A (X tile [128][128]) hi/lo
        {
            int row = tid >> 2, k0 = (tid & 3) * 32;
            int gm = m0 + row;
            #pragma unroll
            for (int c = 0; c < 32; c += 2) {
                float2 xv = make_float2(0.f, 0.f);
                if (gm < N_NODES) xv = *(const float2*)&X[(size_t)gm * ND + k0 + c];
                __nv_bfloat16 h0, l0, h1, l1;
                split_bf16(xv.x, h0, l0); split_bf16(xv.y, h1, l1);
                *(__nv_bfloat162*)(smem + N_AH + (row * NSTR + k0 + c) * 2) = __nv_bfloat162(h0, h1);
                *(__nv_bfloat162*)(smem + N_AL + (row * NSTR + k0 + c) * 2) = __nv_bfloat162(l0, l1);
            }
        }
        __syncthreads();

        float acc[16][4];
        #pragma unroll
        for (int i = 0; i < 16; i++)
            #pragma unroll
            for (int j = 0; j < 4; j++) acc[i][j] = 0.f;

        #pragma unroll
        for (int kk = 0; kk < 8; kk++) {
            u32 ah0, ah1, ah2, ah3, al0, al1, al2, al3;
            ldsm4(aH + kk * 32, ah0, ah1, ah2, ah3);
            ldsm4(aL + kk * 32, al0, al1, al2, al3);
            #pragma unroll
            for (int nt = 0; nt < 16; nt++) {
                u32 bh0, bh1, bl0, bl1;
                ldsm2(bH + nt * (8 * NSTR * 2) + kk * 32, bh0, bh1);
                ldsm2(bL + nt * (8 * NSTR * 2) + kk * 32, bl0, bl1);
                mma16816(acc[nt], ah0, ah1, ah2, ah3, bh0, bh1);
                mma16816(acc[nt], al0, al1, al2, al3, bh0, bh1);
                mma16816(acc[nt], ah0, ah1, ah2, ah3, bl0, bl1);
            }
        }

        // store D directly to g_P
        int nodeLo = m0 + egrp * 16 + (lane >> 2);
        int jbase = n0 + jgrp * 128 + (lane & 3) * 2;
        #pragma unroll
        for (int nt = 0; nt < 16; nt++) {
            if (nodeLo < N_NODES)
                *(float2*)&g_P[(size_t)nodeLo * 512 + jbase + nt * 8] =
                    make_float2(acc[nt][0], acc[nt][1]);
            if (nodeLo + 8 < N_NODES)
                *(float2*)&g_P[(size_t)(nodeLo + 8) * 512 + jbase + nt * 8] =
                    make_float2(acc[nt][2], acc[nt][3]);
        }
        __syncthreads();
    }
}

// ---------------------------------------------------------------------------
// Edge kernel (persistent, HMMA bf16x3 + fused epilogue):
//   tile = 64 edges; D[64,256] = ef @ We^T (hi/lo x3), staged to smem;
//   epilogue warp-per-edge: coalesced P gathers, activations, red.v4 scatter.
// 512 thr = 16 warps; warp = 16e x 64j (egrp = wid>>2, jgrp = wid&3).
// ---------------------------------------------------------------------------
#define ESTR 72                     // padded bf16 row stride (64 + 8)
#define E_BH 0
#define E_BL 36864
#define E_AH 73728
#define E_AL 82944
#define E_STG 92160                 // [64 e][260 floats] (pad: 65 float4/row)
#define E_IDX 158720
#define EDGE_SMEM 159744

__global__ __launch_bounds__(512, 1) void edge_kernel(
    const float* __restrict__ ef, const int* __restrict__ ei,
    const float* __restrict__ b_val, const float* __restrict__ b_mul,
    float* __restrict__ out)
{
    extern __shared__ char smem[];
    u32 sb = smem_u32(smem);
    int tid = threadIdx.x, wid = tid >> 5, lane = tid & 31;
    float* stgf = (float*)(smem + E_STG);
    int* s_sh = (int*)(smem + E_IDX);
    int* r_sh = s_sh + 64;

    // fill B (We [256][64]) hi/lo once
    {
        int j = tid >> 1, k0 = (tid & 1) * 32;
        #pragma unroll
        for (int c = 0; c < 32; c += 2) {
            __nv_bfloat162 h2, l2;
            h2.x = g_WeH[j * 64 + k0 + c]; h2.y = g_WeH[j * 64 + k0 + c + 1];
            l2.x = g_WeL[j * 64 + k0 + c]; l2.y = g_WeL[j * 64 + k0 + c + 1];
            *(__nv_bfloat162*)(smem + E_BH + (j * ESTR + k0 + c) * 2) = h2;
            *(__nv_bfloat162*)(smem + E_BL + (j * ESTR + k0 + c) * 2) = l2;
        }
    }

    const float4 bv4 = *(const float4*)&b_val[4 * lane];
    const float4 bm4 = *(const float4*)&b_mul[4 * lane];

    int egrp = wid >> 2, jgrp = wid & 3;
    u32 aH = sb + E_AH + ((egrp * 16 + (lane & 15)) * ESTR + (lane >> 4) * 8) * 2;
    u32 aL = sb + E_AL + ((egrp * 16 + (lane & 15)) * ESTR + (lane >> 4) * 8) * 2;
    u32 bH = sb + E_BH + ((jgrp * 64 + (lane & 7)) * ESTR + (lane & 8)) * 2;
    u32 bL = sb + E_BL + ((jgrp * 64 + (lane & 7)) * ESTR + (lane & 8)) * 2;

    const int ntiles = N_EDGES / 64;   // 12500
    for (int tile = blockIdx.x; tile < ntiles; tile += gridDim.x) {
        int e0 = tile * 64;
        if (tid < 64)       s_sh[tid] = ei[e0 + tid];
        else if (tid < 128) r_sh[tid - 64] = ei[N_EDGES + e0 + tid - 64];

        // fill A (ef tile [64][64]) hi/lo
        {
            int e = tid >> 3, k0 = (tid & 7) * 8;
            const float2* src = (const float2*)&ef[(size_t)(e0 + e) * ED + k0];
            #pragma unroll
            for (int c = 0; c < 8; c += 2) {
                float2 xv = src[c >> 1];
                __nv_bfloat16 h0, l0, h1, l1;
                split_bf16(xv.x, h0, l0); split_bf16(xv.y, h1, l1);
                *(__nv_bfloat162*)(smem + E_AH + (e * ESTR + k0 + c) * 2) = __nv_bfloat162(h0, h1);
                *(__nv_bfloat162*)(smem + E_AL + (e * ESTR + k0 + c) * 2) = __nv_bfloat162(l0, l1);
            }
        }
        __syncthreads();

        float acc[8][4];
        #pragma unroll
        for (int i = 0; i < 8; i++)
            #pragma unroll
            for (int j = 0; j < 4; j++) acc[i][j] = 0.f;

        #pragma unroll
        for (int kk = 0; kk < 4; kk++) {
            u32 ah0, ah1, ah2, ah3, al0, al1, al2, al3;
            ldsm4(aH + kk * 32, ah0, ah1, ah2, ah3);
            ldsm4(aL + kk * 32, al0, al1, al2, al3);
            #pragma unroll
            for (int nt = 0; nt < 8; nt++) {
                u32 bh0, bh1, bl0, bl1;
                ldsm2(bH + nt * (8 * ESTR * 2) + kk * 32, bh0, bh1);
                ldsm2(bL + nt * (8 * ESTR * 2) + kk * 32, bl0, bl1);
                mma16816(acc[nt], ah0, ah1, ah2, ah3, bh0, bh1);
                mma16816(acc[nt], al0, al1, al2, al3, bh0, bh1);
                mma16816(acc[nt], ah0, ah1, ah2, ah3, bl0, bl1);
            }
        }

        // stage D -> smem
        {
            int eLo = egrp * 16 + (lane >> 2);
            int jb = jgrp * 64 + (lane & 3) * 2;
            #pragma unroll
            for (int nt = 0; nt < 8; nt++) {
                *(float2*)&stgf[eLo * 260 + jb + nt * 8] = make_float2(acc[nt][0], acc[nt][1]);
                *(float2*)&stgf[(eLo + 8) * 260 + jb + nt * 8] = make_float2(acc[nt][2], acc[nt][3]);
            }
        }
        __syncthreads();

        // epilogue: warp-per-edge (4 iterations x 16 warps = 64 edges)
        #pragma unroll 1
        for (int it = 0; it < 4; it++) {
            int e = it * 16 + wid;
            float4 dv = *(const float4*)&stgf[e * 260 + 4 * lane];
            float4 dm = *(const float4*)&stgf[e * 260 + 128 + 4 * lane];
            int s = s_sh[e];
            int r = r_sh[e];
            const float4 psv = *(const float4*)&g_P[(size_t)s * 512 + 4 * lane];
            const float4 prv = *(const float4*)&g_P[(size_t)r * 512 + 128 + 4 * lane];
            const float4 psm = *(const float4*)&g_P[(size_t)s * 512 + 256 + 4 * lane];
            const float4 prm = *(const float4*)&g_P[(size_t)r * 512 + 384 + 4 * lane];

            float v0 = dv.x + psv.x + prv.x + bv4.x;
            float v1 = dv.y + psv.y + prv.y + bv4.y;
            float v2 = dv.z + psv.z + prv.z + bv4.z;
            float v3 = dv.w + psv.w + prv.w + bv4.w;
            float m0 = dm.x + psm.x + prm.x + bm4.x;
            float m1 = dm.y + psm.y + prm.y + bm4.y;
            float m2 = dm.z + psm.z + prm.z + bm4.z;
            float m3 = dm.w + psm.w + prm.w + bm4.w;

            float g0 = softplus_f(v0) * sigmoid_f(m0);
            float g1 = softplus_f(v1) * sigmoid_f(m1);
            float g2 = softplus_f(v2) * sigmoid_f(m2);
            float g3 = softplus_f(v3) * sigmoid_f(m3);

            red4(out + (size_t)r * ND + 4 * lane, g0, g1, g2, g3);
        }
        __syncthreads();
    }
}

// ---------------------------------------------------------------------------
extern "C" void kernel_launch(void* const* d_in, const int* in_sizes, int n_in,
                              void* d_out, int out_size) {
    const float* x  = (const float*)d_in[0];
    const int*   ei = (const int*)  d_in[1];
    const float* ef = (const float*)d_in[2];
    const float* Wv = (const float*)d_in[3];
    const float* bv = (const float*)d_in[4];
    const float* Wm = (const float*)d_in[5];
    const float* bm = (const float*)d_in[6];
    float* out = (float*)d_out;

    cudaFuncSetAttribute(node_gemm_kernel,
                         cudaFuncAttributeMaxDynamicSharedMemorySize, NODE_SMEM);
    cudaFuncSetAttribute(edge_kernel,
                         cudaFuncAttributeMaxDynamicSharedMemorySize, EDGE_SMEM);

    pack_weights_kernel<<<256, 256>>>(Wv, Wm);

    int n4 = N_NODES * ND / 4;
    zero_out_kernel<<<(n4 + 255) / 256, 256>>>((float4*)out, n4);

    node_gemm_kernel<<<dim3(74, 2), 512, NODE_SMEM>>>(x);

    edge_kernel<<<148, 512, EDGE_SMEM>>>(ef, ei, bv, bm, out);
}